// round 15
// baseline (speedup 1.0000x reference)
#include <cuda_runtime.h>
#include <cuda_bf16.h>
#include <cstdint>

// ---------------- problem constants ----------------
#define B_  8
#define S_  1024
#define D_  1024
#define H_  16
#define DH_ 64
#define R_  256
#define KC_ 16
#define KE_ 8

// ---------------- scratch (device globals) ----------
__device__ float g_logits[B_ * S_ * 256];
__device__ float g_tw[4 * B_ * 16];
__device__ int   g_ti[4 * B_ * 16];
__device__ __nv_bfloat16 g_xhi[B_ * S_ * D_],  g_xlo[B_ * S_ * D_];
__device__ __nv_bfloat16 g_whi[256 * D_],      g_wlo[256 * D_];
__device__ __nv_bfloat16 g_schi[B_ * R_ * D_], g_sclo[B_ * R_ * D_];
__device__ __nv_bfloat16 g_hhi[B_ * S_ * R_],  g_hlo[B_ * S_ * R_];
__device__ __nv_bfloat16 g_ehi[B_ * 3 * D_ * R_], g_elo[B_ * 3 * D_ * R_];
__device__ __nv_bfloat16 g_qhi[B_ * S_ * 3 * D_], g_qlo[B_ * S_ * 3 * D_];
__device__ __nv_bfloat16 g_aohi[B_ * S_ * D_], g_aolo[B_ * S_ * D_];
__device__ __nv_bfloat16 g_wohi[D_ * D_],      g_wolo[D_ * D_];

// ---------------- helpers ----------------
__device__ __forceinline__ uint32_t smem_u32(const void* p) {
    uint32_t a;
    asm("{ .reg .u64 t; cvta.to.shared.u64 t, %1; cvt.u32.u64 %0, t; }"
        : "=r"(a) : "l"(p));
    return a;
}
__device__ __forceinline__ void split2(float x, float y, uint32_t& hi, uint32_t& lo) {
    __nv_bfloat16 hx = __float2bfloat16(x);
    __nv_bfloat16 hy = __float2bfloat16(y);
    __nv_bfloat16 lx = __float2bfloat16(x - __bfloat162float(hx));
    __nv_bfloat16 ly = __float2bfloat16(y - __bfloat162float(hy));
    hi = ((uint32_t)__bfloat16_as_ushort(hy) << 16) | __bfloat16_as_ushort(hx);
    lo = ((uint32_t)__bfloat16_as_ushort(ly) << 16) | __bfloat16_as_ushort(lx);
}
__device__ __forceinline__ void ldm_x4(uint32_t* r, uint32_t addr) {
    asm volatile("ldmatrix.sync.aligned.m8n8.x4.shared.b16 {%0,%1,%2,%3}, [%4];"
        : "=r"(r[0]), "=r"(r[1]), "=r"(r[2]), "=r"(r[3]) : "r"(addr));
}
__device__ __forceinline__ void ldm_x4t(uint32_t* r, uint32_t addr) {
    asm volatile("ldmatrix.sync.aligned.m8n8.x4.trans.shared.b16 {%0,%1,%2,%3}, [%4];"
        : "=r"(r[0]), "=r"(r[1]), "=r"(r[2]), "=r"(r[3]) : "r"(addr));
}
__device__ __forceinline__ void mma16816(float* d, const uint32_t* a, const uint32_t* b) {
    asm volatile(
        "mma.sync.aligned.m16n8k16.row.col.f32.bf16.bf16.f32 "
        "{%0,%1,%2,%3}, {%4,%5,%6,%7}, {%8,%9}, {%0,%1,%2,%3};"
        : "+f"(d[0]), "+f"(d[1]), "+f"(d[2]), "+f"(d[3])
        : "r"(a[0]), "r"(a[1]), "r"(a[2]), "r"(a[3]), "r"(b[0]), "r"(b[1]));
}
#define CP16(dst, src) \
    asm volatile("cp.async.cg.shared.global [%0], [%1], 16;" :: "r"(dst), "l"(src))
#define CPCOMMIT() asm volatile("cp.async.commit_group;" ::: "memory")
#define CPWAIT1()  asm volatile("cp.async.wait_group 1;" ::: "memory")
#define CPWAIT0()  asm volatile("cp.async.wait_group 0;" ::: "memory")

// =======================================================================
// bf16-input split GEMM (proven R10 config): C = A @ B^T
// 128x128 CTA tile, BK=32, 256 threads, cp.async double buffer, 2 CTA/SM.
// =======================================================================
#define GPITCH 40
#define TILE_BYTES (128 * GPITCH * 2)      // 10240
#define STAGE_BYTES (4 * TILE_BYTES)       // 40960
#define GEMM_SMEM (2 * STAGE_BYTES)        // 81920

template <int OSPLIT>
__global__ __launch_bounds__(256, 2) void mma_gemm_bf(
    const __nv_bfloat16* __restrict__ Ah, const __nv_bfloat16* __restrict__ Al,
    const __nv_bfloat16* __restrict__ Bh, const __nv_bfloat16* __restrict__ Bl,
    float* __restrict__ C, __nv_bfloat16* __restrict__ Ch, __nv_bfloat16* __restrict__ Cl,
    int M, int N, int K, long long sA, long long sB, long long sC)
{
    extern __shared__ char sm[];
    const uint32_t smb = smem_u32(sm);
    const int tid = threadIdx.x, wid = tid >> 5, lane = tid & 31;

    const size_t zo = (size_t)blockIdx.z;
    const __nv_bfloat16* Ahb = Ah + zo * sA;
    const __nv_bfloat16* Alb = Al + zo * sA;
    const __nv_bfloat16* Bhb = Bh + zo * sB;
    const __nv_bfloat16* Blb = Bl + zo * sB;
    const int m0 = blockIdx.x * 128, n0 = blockIdx.y * 128;

    const int warp_m = wid >> 2, warp_n = wid & 3;
    const int mbase = warp_m * 64, nbase = warp_n * 32;

    float acc[4][4][4];
#pragma unroll
    for (int i = 0; i < 4; i++)
#pragma unroll
        for (int j = 0; j < 4; j++)
#pragma unroll
            for (int q = 0; q < 4; q++) acc[i][j][q] = 0.f;

    const int nst = K >> 5;

    auto issue = [&](int s) {
        const int k0 = s << 5;
        const uint32_t sb = smb + (uint32_t)(s & 1) * STAGE_BYTES;
        const __nv_bfloat16* srcs[4] = {
            Ahb + (size_t)m0 * K + k0, Alb + (size_t)m0 * K + k0,
            Bhb + (size_t)n0 * K + k0, Blb + (size_t)n0 * K + k0 };
#pragma unroll
        for (int q = 0; q < 8; ++q) {
            const int c = q * 256 + tid;
            const int tile = c >> 9, rem = c & 511;
            const int row = rem >> 2, c16 = rem & 3;
            const uint32_t dst = sb + tile * TILE_BYTES + row * (GPITCH * 2) + c16 * 16;
            const __nv_bfloat16* src = srcs[tile] + (size_t)row * K + c16 * 8;
            CP16(dst, src);
        }
    };

    issue(0); CPCOMMIT();

    const int a_row = lane & 15;
    const int a_kad = (lane >> 4) << 3;
    const int b_row = (lane & 7) + ((lane & 16) >> 1);
    const int b_kad = lane & 8;

    for (int s = 0; s < nst; ++s) {
        if (s + 1 < nst) { issue(s + 1); CPCOMMIT(); CPWAIT1(); }
        else             { CPWAIT0(); }
        __syncthreads();
        const uint32_t base = smb + (uint32_t)(s & 1) * STAGE_BYTES;
#pragma unroll
        for (int ks = 0; ks < 2; ++ks) {
            uint32_t ah[4][4], al[4][4], bh[4][2], bl[4][2];
            const int acol = (ks << 4) + a_kad;
            const int bcol = (ks << 4) + b_kad;
#pragma unroll
            for (int am = 0; am < 4; ++am) {
                const uint32_t off = (mbase + am * 16 + a_row) * (GPITCH * 2) + acol * 2;
                ldm_x4(ah[am], base + off);
                ldm_x4(al[am], base + TILE_BYTES + off);
            }
#pragma unroll
            for (int bg = 0; bg < 2; ++bg) {
                uint32_t r[4];
                const uint32_t off = (nbase + bg * 16 + b_row) * (GPITCH * 2) + bcol * 2;
                ldm_x4(r, base + 2 * TILE_BYTES + off);
                bh[bg * 2][0] = r[0]; bh[bg * 2][1] = r[1];
                bh[bg * 2 + 1][0] = r[2]; bh[bg * 2 + 1][1] = r[3];
                ldm_x4(r, base + 3 * TILE_BYTES + off);
                bl[bg * 2][0] = r[0]; bl[bg * 2][1] = r[1];
                bl[bg * 2 + 1][0] = r[2]; bl[bg * 2 + 1][1] = r[3];
            }
#pragma unroll
            for (int am = 0; am < 4; ++am)
#pragma unroll
                for (int bn = 0; bn < 4; ++bn) {
                    mma16816(acc[am][bn], ah[am], bh[bn]);
                    mma16816(acc[am][bn], ah[am], bl[bn]);
                    mma16816(acc[am][bn], al[am], bh[bn]);
                }
        }
        __syncthreads();
    }

    const int erow = lane >> 2, ecol = (lane & 3) << 1;
#pragma unroll
    for (int am = 0; am < 4; ++am) {
        const int r0 = m0 + mbase + am * 16 + erow;
#pragma unroll
        for (int bn = 0; bn < 4; ++bn) {
            const int c0 = n0 + nbase + bn * 8 + ecol;
            if (OSPLIT == 0) {
                float* Cb = C + zo * sC;
                *(float2*)&Cb[(size_t)r0 * N + c0] =
                    make_float2(acc[am][bn][0], acc[am][bn][1]);
                *(float2*)&Cb[(size_t)(r0 + 8) * N + c0] =
                    make_float2(acc[am][bn][2], acc[am][bn][3]);
            } else {
                __nv_bfloat16* Chb = Ch + zo * sC;
                __nv_bfloat16* Clb = Cl + zo * sC;
                uint32_t h01, l01, h23, l23;
                split2(acc[am][bn][0], acc[am][bn][1], h01, l01);
                split2(acc[am][bn][2], acc[am][bn][3], h23, l23);
                *(uint32_t*)&Chb[(size_t)r0 * N + c0]       = h01;
                *(uint32_t*)&Clb[(size_t)r0 * N + c0]       = l01;
                *(uint32_t*)&Chb[(size_t)(r0 + 8) * N + c0] = h23;
                *(uint32_t*)&Clb[(size_t)(r0 + 8) * N + c0] = l23;
            }
        }
    }
}

// ---------------- one-time split kernels ----------------
__global__ void split4_kernel(const float* __restrict__ src,
                              __nv_bfloat16* __restrict__ hi,
                              __nv_bfloat16* __restrict__ lo, int n4)
{
    const int i = blockIdx.x * 256 + threadIdx.x;
    if (i >= n4) return;
    float4 v = ((const float4*)src)[i];
    uint32_t h01, l01, h23, l23;
    split2(v.x, v.y, h01, l01);
    split2(v.z, v.w, h23, l23);
    ((uint2*)hi)[i] = make_uint2(h01, h23);
    ((uint2*)lo)[i] = make_uint2(l01, l23);
}

__global__ void concat_split_kernel(const float* __restrict__ a, const float* __restrict__ b,
                                    const float* __restrict__ c, const float* __restrict__ d)
{
    const int i4 = blockIdx.x * 256 + threadIdx.x;
    const int rt = i4 >> 14, rem = i4 & 16383;
    const float* src = (rt == 0) ? a : (rt == 1) ? b : (rt == 2) ? c : d;
    float4 v = ((const float4*)src)[rem];
    uint32_t h01, l01, h23, l23;
    split2(v.x, v.y, h01, l01);
    split2(v.z, v.w, h23, l23);
    ((uint2*)g_whi)[i4] = make_uint2(h01, h23);
    ((uint2*)g_wlo)[i4] = make_uint2(l01, l23);
}

// ---------------- router ----------------
__global__ void router_kernel(const float* __restrict__ importance)
{
    const int rt = blockIdx.x, b = blockIdx.y;
    const int k = (rt == 0) ? KC_ : KE_;
    __shared__ float wpart[8][64];
    __shared__ float w[64];
    const int tid = threadIdx.x, warp = tid >> 5, lane = tid & 31;

    float acc0 = 0.f, acc1 = 0.f;
    for (int s = warp; s < S_; s += 8) {
        const float* lp = g_logits + ((long long)(b * S_ + s)) * 256 + rt * 64;
        float v0 = lp[lane], v1 = lp[lane + 32];
        float mx = fmaxf(v0, v1);
#pragma unroll
        for (int off = 16; off; off >>= 1) mx = fmaxf(mx, __shfl_xor_sync(~0u, mx, off));
        float e0 = __expf(v0 - mx), e1 = __expf(v1 - mx);
        float smv = e0 + e1;
#pragma unroll
        for (int off = 16; off; off >>= 1) smv += __shfl_xor_sync(~0u, smv, off);
        float c = importance[b * S_ + s] / smv;
        acc0 += e0 * c;
        acc1 += e1 * c;
    }
    wpart[warp][lane]      = acc0;
    wpart[warp][lane + 32] = acc1;
    __syncthreads();
    if (tid < 64) {
        float t = 0.f;
#pragma unroll
        for (int wi = 0; wi < 8; wi++) t += wpart[wi][tid];
        w[tid] = t;
    }
    __syncthreads();
    if (tid == 0) {
        float tot = 0.f;
        for (int n = 0; n < 64; n++) tot += w[n];
        const float inv = 1.f / (tot + 1e-8f);
        float tw[16]; int ti[16]; bool used[64];
        for (int n = 0; n < 64; n++) used[n] = false;
        for (int kk = 0; kk < k; kk++) {
            float best = -1e30f; int bi = 0;
            for (int n = 0; n < 64; n++) {
                float v = w[n] * inv;
                if (!used[n] && v > best) { best = v; bi = n; }
            }
            used[bi] = true; tw[kk] = best; ti[kk] = bi;
        }
        float ts = 0.f;
        for (int kk = 0; kk < k; kk++) ts += tw[kk];
        const float inv2 = 1.f / (ts + 1e-8f);
        for (int kk = 0; kk < k; kk++) {
            g_tw[(rt * B_ + b) * 16 + kk] = tw[kk] * inv2;
            g_ti[(rt * B_ + b) * 16 + kk] = ti[kk];
        }
    }
}

// ---------------- mix compress -> split bf16 [b][r][d] -----
__global__ void mix_compressT_kernel(const float* __restrict__ cn)
{
    const int b = blockIdx.y;
    const int dt = blockIdx.x >> 3, rt = blockIdx.x & 7;
    const int d0 = dt * 32, r0 = rt * 32;
    __shared__ float cw[KC_]; __shared__ int ci[KC_];
    __shared__ float ts[32][33];
    if (threadIdx.x < KC_) {
        cw[threadIdx.x] = g_tw[(0 * B_ + b) * 16 + threadIdx.x];
        ci[threadIdx.x] = g_ti[(0 * B_ + b) * 16 + threadIdx.x];
    }
    __syncthreads();
    const int tid = threadIdx.x;
    const int dd = tid >> 3, rr = (tid & 7) << 2;
    float4 acc = {0.f, 0.f, 0.f, 0.f};
#pragma unroll
    for (int kk = 0; kk < KC_; kk++) {
        const float4 v = *(const float4*)(cn + ((size_t)ci[kk] * D_ + d0 + dd) * R_ + r0 + rr);
        const float wv = cw[kk];
        acc.x += wv * v.x; acc.y += wv * v.y; acc.z += wv * v.z; acc.w += wv * v.w;
    }
    ts[dd][rr] = acc.x; ts[dd][rr + 1] = acc.y; ts[dd][rr + 2] = acc.z; ts[dd][rr + 3] = acc.w;
    __syncthreads();
    const int rw = tid >> 3, dw = (tid & 7) << 2;
    float4 o = {ts[dw][rw], ts[dw + 1][rw], ts[dw + 2][rw], ts[dw + 3][rw]};
    uint32_t h01, l01, h23, l23;
    split2(o.x, o.y, h01, l01);
    split2(o.z, o.w, h23, l23);
    const size_t base = ((size_t)b * R_ + r0 + rw) * D_ + d0 + dw;
    *(uint2*)&g_schi[base] = make_uint2(h01, h23);
    *(uint2*)&g_sclo[base] = make_uint2(l01, l23);
}

// ---------------- mix expand -> split bf16 [b][3D][r] --
__global__ void mix_expandT_kernel(const float* __restrict__ pool)
{
    const int which = blockIdx.y, b = blockIdx.z;
    const int dt = blockIdx.x >> 3, rt = blockIdx.x & 7;
    const int d0 = dt * 32, r0 = rt * 32;
    const int rtr = which + 1;
    __shared__ float ew[KE_]; __shared__ int ei[KE_];
    __shared__ float ts[32][33];
    if (threadIdx.x < KE_) {
        ew[threadIdx.x] = g_tw[(rtr * B_ + b) * 16 + threadIdx.x];
        ei[threadIdx.x] = g_ti[(rtr * B_ + b) * 16 + threadIdx.x];
    }
    __syncthreads();
    const int tid = threadIdx.x;
    const int rr = tid >> 3, dd = (tid & 7) << 2;
    float4 acc = {0.f, 0.f, 0.f, 0.f};
#pragma unroll
    for (int kk = 0; kk < KE_; kk++) {
        const float4 v = *(const float4*)(pool + ((size_t)ei[kk] * R_ + r0 + rr) * D_ + d0 + dd);
        const float wv = ew[kk];
        acc.x += wv * v.x; acc.y += wv * v.y; acc.z += wv * v.z; acc.w += wv * v.w;
    }
    ts[rr][dd] = acc.x; ts[rr][dd + 1] = acc.y; ts[rr][dd + 2] = acc.z; ts[rr][dd + 3] = acc.w;
    __syncthreads();
    const int dw = tid >> 3, rw = (tid & 7) << 2;
    float4 o = {ts[rw][dw], ts[rw + 1][dw], ts[rw + 2][dw], ts[rw + 3][dw]};
    uint32_t h01, l01, h23, l23;
    split2(o.x, o.y, h01, l01);
    split2(o.z, o.w, h23, l23);
    const size_t base = ((size_t)b * 3 * D_ + (size_t)which * D_ + d0 + dw) * R_ + r0 + rw;
    *(uint2*)&g_ehi[base] = make_uint2(h01, h23);
    *(uint2*)&g_elo[base] = make_uint2(l01, l23);
}

// =======================================================================
// flash attention (R10 config + longest-first CTA order), 2 CTA/SM
// =======================================================================
#define FPX 72
#define FQHI 0
#define FQLO (128 * FPX)
#define FKV0 (256 * FPX)
#define KVSZ (256 * FPX)
#define FLASH_SMEM ((FKV0 + 2 * KVSZ) * 2)     // 110592 bytes
#define SC2L 0.18033688011112042f

__global__ __launch_bounds__(256, 2) void flash_mma_bf(
    const __nv_bfloat16* __restrict__ qh, const __nv_bfloat16* __restrict__ ql,
    __nv_bfloat16* __restrict__ oh, __nv_bfloat16* __restrict__ ol)
{
    extern __shared__ char smc[];
    const uint32_t smb = smem_u32(smc);
    const int tid = threadIdx.x, w = tid >> 5, lane = tid & 31;
    const int b = blockIdx.y >> 4, h = blockIdx.y & 15;
    // longest-first: heavy (large q0) CTAs get scheduled in the first wave
    const int q0 = (gridDim.x - 1 - blockIdx.x) * 128;
    const size_t bbase = (size_t)b * S_ * (3 * D_) + h * DH_;

    auto issue_kv = [&](int t) {
        const int k0 = t * 64;
        const uint32_t kvb = (uint32_t)(FKV0 + (t & 1) * KVSZ);
#pragma unroll
        for (int q = 0; q < 8; ++q) {
            const int c = q * 256 + tid;
            const int tile = c >> 9, rem = c & 511;
            const int row = rem >> 3, c16 = rem & 7;
            const uint32_t dst = smb + 2 * (kvb + tile * (64 * FPX) + row * FPX) + c16 * 16;
            const __nv_bfloat16* sp = (tile & 1) ? ql : qh;
            const size_t goff = bbase + ((tile >> 1) ? 2 * D_ : D_)
                                + (size_t)(k0 + row) * (3 * D_) + c16 * 8;
            CP16(dst, sp + goff);
        }
    };

#pragma unroll
    for (int q = 0; q < 8; ++q) {
        const int c = q * 256 + tid;
        const int arr = c >> 10, rem = c & 1023;
        const int row = rem >> 3, c16 = rem & 7;
        const uint32_t dst = smb + (arr ? FQLO : FQHI) * 2 + row * (FPX * 2) + c16 * 16;
        const __nv_bfloat16* src = (arr ? ql : qh) + bbase
                                   + (size_t)(q0 + row) * (3 * D_) + c16 * 8;
        CP16(dst, src);
    }
    issue_kv(0); CPCOMMIT();

    float sacc[8][4], oacc[8][4];
    float m0v = -1e30f, m1v = -1e30f, l0v = 0.f, l1v = 0.f;
#pragma unroll
    for (int t = 0; t < 8; t++)
#pragma unroll
        for (int e = 0; e < 4; e++) oacc[t][e] = 0.f;

    const int a_row = lane & 15;
    const int a_kad = (lane >> 4) << 3;
    const int b_row = (lane & 7) + ((lane & 16) >> 1);
    const int b_kad = lane & 8;
    const int qwarp = q0 + w * 16;
    const int r0 = lane >> 2;
    const int c0l = (lane & 3) << 1;

    const int ntiles = (q0 + 128) >> 6;
    for (int t = 0; t < ntiles; ++t) {
        const int k0 = t * 64;
        if (t + 1 < ntiles) { issue_kv(t + 1); CPCOMMIT(); CPWAIT1(); }
        else                { CPWAIT0(); }
        __syncthreads();

        if (k0 <= qwarp + 15) {
            const uint32_t kv = (uint32_t)(FKV0 + (t & 1) * KVSZ);
#pragma unroll
            for (int tt = 0; tt < 8; tt++)
#pragma unroll
                for (int e = 0; e < 4; e++) sacc[tt][e] = 0.f;
#pragma unroll
            for (int kk = 0; kk < 4; ++kk) {
                uint32_t qhf[4], qlf[4];
                const uint32_t qoff = 2 * (uint32_t)((w * 16 + a_row) * FPX + kk * 16 + a_kad);
                ldm_x4(qhf, smb + 2 * FQHI + qoff);
                ldm_x4(qlf, smb + 2 * FQLO + qoff);
#pragma unroll
                for (int jt = 0; jt < 4; ++jt) {
                    uint32_t khf[4], klf[4];
                    const uint32_t koff = 2 * (uint32_t)(kv + (jt * 16 + b_row) * FPX
                                                         + kk * 16 + b_kad);
                    ldm_x4(khf, smb + koff);
                    ldm_x4(klf, smb + koff + 2 * (64 * FPX));
                    mma16816(sacc[jt * 2],     qhf, khf);
                    mma16816(sacc[jt * 2 + 1], qhf, khf + 2);
                    mma16816(sacc[jt * 2],     qhf, klf);
                    mma16816(sacc[jt * 2 + 1], qhf, klf + 2);
                    mma16816(sacc[jt * 2],     qlf, khf);
                    mma16816(sacc[jt * 2 + 1], qlf, khf + 2);
                }
            }

            if (k0 + 63 > qwarp) {
#pragma unroll
                for (int tt = 0; tt < 8; tt++) {
                    const int kg = k0 + tt * 8 + c0l;
#pragma unroll
                    for (int e = 0; e < 4; e++) {
                        const int kge = kg + (e & 1);
                        const int qg = qwarp + r0 + ((e >> 1) << 3);
                        if (kge > qg) sacc[tt][e] = -1e30f;
                    }
                }
            }

            float mx0 = -1e30f, mx1 = -1e30f;
#pragma unroll
            for (int tt = 0; tt < 8; tt++) {
                mx0 = fmaxf(mx0, fmaxf(sacc[tt][0], sacc[tt][1]));
                mx1 = fmaxf(mx1, fmaxf(sacc[tt][2], sacc[tt][3]));
            }
            mx0 = fmaxf(mx0, __shfl_xor_sync(~0u, mx0, 1));
            mx0 = fmaxf(mx0, __shfl_xor_sync(~0u, mx0, 2));
            mx1 = fmaxf(mx1, __shfl_xor_sync(~0u, mx1, 1));
            mx1 = fmaxf(mx1, __shfl_xor_sync(~0u, mx1, 2));
            const float mn0 = fmaxf(m0v, mx0), mn1 = fmaxf(m1v, mx1);
            const float al0 = exp2f((m0v - mn0) * SC2L);
            const float al1 = exp2f((m1v - mn1) * SC2L);
            float sum0 = 0.f, sum1 = 0.f;
            uint32_t ph[8][2], pl[8][2];
#pragma unroll
            for (int tt = 0; tt < 8; tt++) {
                float p0 = exp2f((sacc[tt][0] - mn0) * SC2L);
                float p1 = exp2f((sacc[tt][1] - mn0) * SC2L);
                float p2 = exp2f((sacc[tt][2] - mn1) * SC2L);
                float p3 = exp2f((sacc[tt][3] - mn1) * SC2L);
                sum0 += p0 + p1; sum1 += p2 + p3;
                split2(p0, p1, ph[tt][0], pl[tt][0]);
                split2(p2, p3, ph[tt][1], pl[tt][1]);
            }
            sum0 += __shfl_xor_sync(~0u, sum0, 1);
            sum0 += __shfl_xor_sync(~0u, sum0, 2);
            sum1 += __shfl_xor_sync(~0u, sum1, 1);
            sum1 += __shfl_xor_sync(~0u, sum1, 2);
            l0v = l0v * al0 + sum0;
            l1v = l1v * al1 + sum1;
            m0v = mn0; m1v = mn1;
#pragma unroll
            for (int tt = 0; tt < 8; tt++) {
                oacc[tt][0] *= al0; oacc[tt][1] *= al0;
                oacc[tt][2] *= al1; oacc[tt][3] *= al1;
            }

#pragma unroll
            for (int g = 0; g < 4; ++g) {
                uint32_t Ahf[4] = {ph[2 * g][0], ph[2 * g][1], ph[2 * g + 1][0], ph[2 * g + 1][1]};
                uint32_t Alf[4] = {pl[2 * g][0], pl[2 * g][1], pl[2 * g + 1][0], pl[2 * g + 1][1]};
#pragma unroll
                for (int dp = 0; dp < 4; ++dp) {
                    uint32_t vhf[4], vlf[4];
                    const uint32_t voff = 2 * (uint32_t)(kv + 128 * FPX
                                                         + (g * 16 + (lane & 15)) * FPX
                                                         + dp * 16 + ((lane >> 4) << 3));
                    ldm_x4t(vhf, smb + voff);
                    ldm_x4t(vlf, smb + voff + 2 * (64 * FPX));
                    mma16816(oacc[dp * 2],     Ahf, vhf);
                    mma16816(oacc[dp * 2 + 1], Ahf, vhf + 2);
                    mma16816(oacc[dp * 2],     Alf, vhf);
                    mma16816(oacc[dp * 2 + 1], Alf, vhf + 2);
                    mma16816(oacc[dp * 2],     Ahf, vlf);
                    mma16816(oacc[dp * 2 + 1], Ahf, vlf + 2);
                }
            }
        }
        __syncthreads();
    }

    const float inv0 = 1.f / l0v, inv1 = 1.f / l1v;
    __nv_bfloat16* ohp = oh + (size_t)b * S_ * D_ + (size_t)h * DH_;
    __nv_bfloat16* olp = ol + (size_t)b * S_ * D_ + (size_t)h * DH_;
    const int row0 = q0 + w * 16 + r0;
#pragma unroll
    for (int t = 0; t < 8; t++) {
        const int c = t * 8 + c0l;
        uint32_t h01, l01, h23, l23;
        split2(oacc[t][0] * inv0, oacc[t][1] * inv0, h01, l01);
        split2(oacc[t][2] * inv1, oacc[t][3] * inv1, h23, l23);
        *(uint32_t*)&ohp[(size_t)row0 * D_ + c]       = h01;
        *(uint32_t*)&olp[(size_t)row0 * D_ + c]       = l01;
        *(uint32_t*)&ohp[(size_t)(row0 + 8) * D_ + c] = h23;
        *(uint32_t*)&olp[(size_t)(row0 + 8) * D_ + c] = l23;
    }
}

// ---------------- launch ----------------
extern "C" void kernel_launch(void* const* d_in, const int* in_sizes, int n_in,
                              void* d_out, int out_size)
{
    const float* x    = (const float*)d_in[0];
    const float* imp  = (const float*)d_in[1];
    const float* Wc   = (const float*)d_in[2];
    const float* Wq   = (const float*)d_in[3];
    const float* Wk   = (const float*)d_in[4];
    const float* Wv   = (const float*)d_in[5];
    const float* cn   = (const float*)d_in[6];
    const float* pool = (const float*)d_in[7];
    const float* WO   = (const float*)d_in[8];
    float* out = (float*)d_out;

    float* pLog;
    __nv_bfloat16 *pxh, *pxl, *pwh, *pwl, *psh, *psl, *phh, *phl;
    __nv_bfloat16 *peh, *pel, *pqh, *pql, *pah, *pal, *poh2, *pol2;
    cudaGetSymbolAddress((void**)&pLog, g_logits);
    cudaGetSymbolAddress((void**)&pxh, g_xhi);  cudaGetSymbolAddress((void**)&pxl, g_xlo);
    cudaGetSymbolAddress((void**)&pwh, g_whi);  cudaGetSymbolAddress((void**)&pwl, g_wlo);
    cudaGetSymbolAddress((void**)&psh, g_schi); cudaGetSymbolAddress((void**)&psl, g_sclo);
    cudaGetSymbolAddress((void**)&phh, g_hhi);  cudaGetSymbolAddress((void**)&phl, g_hlo);
    cudaGetSymbolAddress((void**)&peh, g_ehi);  cudaGetSymbolAddress((void**)&pel, g_elo);
    cudaGetSymbolAddress((void**)&pqh, g_qhi);  cudaGetSymbolAddress((void**)&pql, g_qlo);
    cudaGetSymbolAddress((void**)&pah, g_aohi); cudaGetSymbolAddress((void**)&pal, g_aolo);
    cudaGetSymbolAddress((void**)&poh2, g_wohi); cudaGetSymbolAddress((void**)&pol2, g_wolo);

    cudaFuncSetAttribute(mma_gemm_bf<0>, cudaFuncAttributeMaxDynamicSharedMemorySize, GEMM_SMEM);
    cudaFuncSetAttribute(mma_gemm_bf<1>, cudaFuncAttributeMaxDynamicSharedMemorySize, GEMM_SMEM);
    cudaFuncSetAttribute(flash_mma_bf, cudaFuncAttributeMaxDynamicSharedMemorySize, FLASH_SMEM);

    // side stream + events for graph-captured fork/join (created once)
    static cudaStream_t s2 = nullptr;
    static cudaEvent_t e0 = nullptr, eRt = nullptr, e1 = nullptr;
    if (!s2) {
        cudaStreamCreateWithFlags(&s2, cudaStreamNonBlocking);
        cudaEventCreateWithFlags(&e0,  cudaEventDisableTiming);
        cudaEventCreateWithFlags(&eRt, cudaEventDisableTiming);
        cudaEventCreateWithFlags(&e1,  cudaEventDisableTiming);
    }

    // ---- fork: WO split runs on s2 from the start ----
    cudaEventRecord(e0, 0);
    cudaStreamWaitEvent(s2, e0, 0);
    split4_kernel<<<1024, 256, 0, s2>>>(WO, poh2, pol2, D_ * D_ / 4);

    // main stream: x split, router-weight split, logits, router
    split4_kernel<<<8192, 256>>>(x, pxh, pxl, B_ * S_ * D_ / 4);
    concat_split_kernel<<<256, 256>>>(Wc, Wq, Wk, Wv);
    mma_gemm_bf<0><<<dim3(64, 2, 1), 256, GEMM_SMEM>>>(
        pxh, pxl, pwh, pwl, pLog, nullptr, nullptr, 8192, 256, 1024, 0, 0, 0);
    router_kernel<<<dim3(4, 8), 256>>>(imp);
    cudaEventRecord(eRt, 0);

    // s2: mix_expandT overlaps with mix_compressT + h GEMM on main stream
    cudaStreamWaitEvent(s2, eRt, 0);
    mix_expandT_kernel<<<dim3(256, 3, 8), 256, 0, s2>>>(pool);
    cudaEventRecord(e1, s2);

    // main stream: mix_compressT, h GEMM
    mix_compressT_kernel<<<dim3(256, 8), 256>>>(cn);
    mma_gemm_bf<1><<<dim3(8, 2, 8), 256, GEMM_SMEM>>>(
        pxh, pxl, psh, psl, nullptr, phh, phl, 1024, 256, 1024,
        (long long)S_ * D_, (long long)R_ * D_, (long long)S_ * R_);

    // join before QKV GEMM (needs eAll from s2)
    cudaStreamWaitEvent(0, e1, 0);
    mma_gemm_bf<1><<<dim3(8, 24, 8), 256, GEMM_SMEM>>>(
        phh, phl, peh, pel, nullptr, pqh, pql, 1024, 3 * D_, 256,
        (long long)S_ * R_, (long long)3 * D_ * R_, (long long)S_ * 3 * D_);
    // flash attention (longest-first order)
    flash_mma_bf<<<dim3(8, 128), 256, FLASH_SMEM>>>(pqh, pql, pah, pal);
    // out = aout @ W_O^T (WO split joined via e1 ordering: s2 work precedes e1)
    mma_gemm_bf<0><<<dim3(64, 8, 1), 256, GEMM_SMEM>>>(
        pah, pal, poh2, pol2, out, nullptr, nullptr, 8192, 1024, 1024, 0, 0, 0);
}

// round 16
// speedup vs baseline: 1.0407x; 1.0407x over previous
#include <cuda_runtime.h>
#include <cuda_bf16.h>
#include <cstdint>

// ---------------- problem constants ----------------
#define B_  8
#define S_  1024
#define D_  1024
#define H_  16
#define DH_ 64
#define R_  256
#define KC_ 16
#define KE_ 8

// ---------------- scratch (device globals) ----------
__device__ float g_logits[B_ * S_ * 256];
__device__ float g_part[2 * B_ * S_ * 256];        // split-K partials (2 x 2M floats)
__device__ float g_tw[4 * B_ * 16];
__device__ int   g_ti[4 * B_ * 16];
__device__ __nv_bfloat16 g_xhi[B_ * S_ * D_],  g_xlo[B_ * S_ * D_];
__device__ __nv_bfloat16 g_whi[256 * D_],      g_wlo[256 * D_];
__device__ __nv_bfloat16 g_schi[B_ * R_ * D_], g_sclo[B_ * R_ * D_];
__device__ __nv_bfloat16 g_hhi[B_ * S_ * R_],  g_hlo[B_ * S_ * R_];
__device__ __nv_bfloat16 g_ehi[B_ * 3 * D_ * R_], g_elo[B_ * 3 * D_ * R_];
__device__ __nv_bfloat16 g_qhi[B_ * S_ * 3 * D_], g_qlo[B_ * S_ * 3 * D_];
__device__ __nv_bfloat16 g_aohi[B_ * S_ * D_], g_aolo[B_ * S_ * D_];
__device__ __nv_bfloat16 g_wohi[D_ * D_],      g_wolo[D_ * D_];

// ---------------- helpers ----------------
__device__ __forceinline__ uint32_t smem_u32(const void* p) {
    uint32_t a;
    asm("{ .reg .u64 t; cvta.to.shared.u64 t, %1; cvt.u32.u64 %0, t; }"
        : "=r"(a) : "l"(p));
    return a;
}
__device__ __forceinline__ void split2(float x, float y, uint32_t& hi, uint32_t& lo) {
    __nv_bfloat16 hx = __float2bfloat16(x);
    __nv_bfloat16 hy = __float2bfloat16(y);
    __nv_bfloat16 lx = __float2bfloat16(x - __bfloat162float(hx));
    __nv_bfloat16 ly = __float2bfloat16(y - __bfloat162float(hy));
    hi = ((uint32_t)__bfloat16_as_ushort(hy) << 16) | __bfloat16_as_ushort(hx);
    lo = ((uint32_t)__bfloat16_as_ushort(ly) << 16) | __bfloat16_as_ushort(lx);
}
__device__ __forceinline__ void ldm_x4(uint32_t* r, uint32_t addr) {
    asm volatile("ldmatrix.sync.aligned.m8n8.x4.shared.b16 {%0,%1,%2,%3}, [%4];"
        : "=r"(r[0]), "=r"(r[1]), "=r"(r[2]), "=r"(r[3]) : "r"(addr));
}
__device__ __forceinline__ void ldm_x4t(uint32_t* r, uint32_t addr) {
    asm volatile("ldmatrix.sync.aligned.m8n8.x4.trans.shared.b16 {%0,%1,%2,%3}, [%4];"
        : "=r"(r[0]), "=r"(r[1]), "=r"(r[2]), "=r"(r[3]) : "r"(addr));
}
__device__ __forceinline__ void mma16816(float* d, const uint32_t* a, const uint32_t* b) {
    asm volatile(
        "mma.sync.aligned.m16n8k16.row.col.f32.bf16.bf16.f32 "
        "{%0,%1,%2,%3}, {%4,%5,%6,%7}, {%8,%9}, {%0,%1,%2,%3};"
        : "+f"(d[0]), "+f"(d[1]), "+f"(d[2]), "+f"(d[3])
        : "r"(a[0]), "r"(a[1]), "r"(a[2]), "r"(a[3]), "r"(b[0]), "r"(b[1]));
}
#define CP16(dst, src) \
    asm volatile("cp.async.cg.shared.global [%0], [%1], 16;" :: "r"(dst), "l"(src))
#define CPCOMMIT() asm volatile("cp.async.commit_group;" ::: "memory")
#define CPWAIT1()  asm volatile("cp.async.wait_group 1;" ::: "memory")
#define CPWAIT0()  asm volatile("cp.async.wait_group 0;" ::: "memory")

// =======================================================================
// bf16-input split GEMM: C = A @ B^T (proven R10 tile config)
// KSPLIT=1: blockIdx.z = (batch<<1)|khalf; each khalf computes K elems
// starting at khalf*K (row stride ldk), writing fp32 partial at
// C + khalf*pOff + batch*sC.   KSPLIT=0: blockIdx.z = batch.
// =======================================================================
#define GPITCH 40
#define TILE_BYTES (128 * GPITCH * 2)      // 10240
#define STAGE_BYTES (4 * TILE_BYTES)       // 40960
#define GEMM_SMEM (2 * STAGE_BYTES)        // 81920

template <int OSPLIT, int KSPLIT>
__global__ __launch_bounds__(256, 2) void mma_gemm_bf(
    const __nv_bfloat16* __restrict__ Ah, const __nv_bfloat16* __restrict__ Al,
    const __nv_bfloat16* __restrict__ Bh, const __nv_bfloat16* __restrict__ Bl,
    float* __restrict__ C, __nv_bfloat16* __restrict__ Ch, __nv_bfloat16* __restrict__ Cl,
    int M, int N, int K, int ldk, long long sA, long long sB, long long sC,
    long long pOff)
{
    extern __shared__ char sm[];
    const uint32_t smb = smem_u32(sm);
    const int tid = threadIdx.x, wid = tid >> 5, lane = tid & 31;

    const int zb = KSPLIT ? (int)(blockIdx.z >> 1) : (int)blockIdx.z;
    const int kh = KSPLIT ? (int)(blockIdx.z & 1) : 0;
    const int koff = kh * K;
    const __nv_bfloat16* Ahb = Ah + (size_t)zb * sA + koff;
    const __nv_bfloat16* Alb = Al + (size_t)zb * sA + koff;
    const __nv_bfloat16* Bhb = Bh + (size_t)zb * sB + koff;
    const __nv_bfloat16* Blb = Bl + (size_t)zb * sB + koff;
    const int m0 = blockIdx.x * 128, n0 = blockIdx.y * 128;

    const int warp_m = wid >> 2, warp_n = wid & 3;
    const int mbase = warp_m * 64, nbase = warp_n * 32;

    float acc[4][4][4];
#pragma unroll
    for (int i = 0; i < 4; i++)
#pragma unroll
        for (int j = 0; j < 4; j++)
#pragma unroll
            for (int q = 0; q < 4; q++) acc[i][j][q] = 0.f;

    const int nst = K >> 5;

    auto issue = [&](int s) {
        const int k0 = s << 5;
        const uint32_t sb = smb + (uint32_t)(s & 1) * STAGE_BYTES;
        const __nv_bfloat16* srcs[4] = {
            Ahb + (size_t)m0 * ldk + k0, Alb + (size_t)m0 * ldk + k0,
            Bhb + (size_t)n0 * ldk + k0, Blb + (size_t)n0 * ldk + k0 };
#pragma unroll
        for (int q = 0; q < 8; ++q) {
            const int c = q * 256 + tid;
            const int tile = c >> 9, rem = c & 511;
            const int row = rem >> 2, c16 = rem & 3;
            const uint32_t dst = sb + tile * TILE_BYTES + row * (GPITCH * 2) + c16 * 16;
            const __nv_bfloat16* src = srcs[tile] + (size_t)row * ldk + c16 * 8;
            CP16(dst, src);
        }
    };

    issue(0); CPCOMMIT();

    const int a_row = lane & 15;
    const int a_kad = (lane >> 4) << 3;
    const int b_row = (lane & 7) + ((lane & 16) >> 1);
    const int b_kad = lane & 8;

    for (int s = 0; s < nst; ++s) {
        if (s + 1 < nst) { issue(s + 1); CPCOMMIT(); CPWAIT1(); }
        else             { CPWAIT0(); }
        __syncthreads();
        const uint32_t base = smb + (uint32_t)(s & 1) * STAGE_BYTES;
#pragma unroll
        for (int ks = 0; ks < 2; ++ks) {
            uint32_t ah[4][4], al[4][4], bh[4][2], bl[4][2];
            const int acol = (ks << 4) + a_kad;
            const int bcol = (ks << 4) + b_kad;
#pragma unroll
            for (int am = 0; am < 4; ++am) {
                const uint32_t off = (mbase + am * 16 + a_row) * (GPITCH * 2) + acol * 2;
                ldm_x4(ah[am], base + off);
                ldm_x4(al[am], base + TILE_BYTES + off);
            }
#pragma unroll
            for (int bg = 0; bg < 2; ++bg) {
                uint32_t r[4];
                const uint32_t off = (nbase + bg * 16 + b_row) * (GPITCH * 2) + bcol * 2;
                ldm_x4(r, base + 2 * TILE_BYTES + off);
                bh[bg * 2][0] = r[0]; bh[bg * 2][1] = r[1];
                bh[bg * 2 + 1][0] = r[2]; bh[bg * 2 + 1][1] = r[3];
                ldm_x4(r, base + 3 * TILE_BYTES + off);
                bl[bg * 2][0] = r[0]; bl[bg * 2][1] = r[1];
                bl[bg * 2 + 1][0] = r[2]; bl[bg * 2 + 1][1] = r[3];
            }
#pragma unroll
            for (int am = 0; am < 4; ++am)
#pragma unroll
                for (int bn = 0; bn < 4; ++bn) {
                    mma16816(acc[am][bn], ah[am], bh[bn]);
                    mma16816(acc[am][bn], ah[am], bl[bn]);
                    mma16816(acc[am][bn], al[am], bh[bn]);
                }
        }
        __syncthreads();
    }

    const int erow = lane >> 2, ecol = (lane & 3) << 1;
#pragma unroll
    for (int am = 0; am < 4; ++am) {
        const int r0 = m0 + mbase + am * 16 + erow;
#pragma unroll
        for (int bn = 0; bn < 4; ++bn) {
            const int c0 = n0 + nbase + bn * 8 + ecol;
            if (OSPLIT == 0) {
                float* Cb = C + (size_t)kh * pOff + (size_t)zb * sC;
                *(float2*)&Cb[(size_t)r0 * N + c0] =
                    make_float2(acc[am][bn][0], acc[am][bn][1]);
                *(float2*)&Cb[(size_t)(r0 + 8) * N + c0] =
                    make_float2(acc[am][bn][2], acc[am][bn][3]);
            } else {
                __nv_bfloat16* Chb = Ch + (size_t)zb * sC;
                __nv_bfloat16* Clb = Cl + (size_t)zb * sC;
                uint32_t h01, l01, h23, l23;
                split2(acc[am][bn][0], acc[am][bn][1], h01, l01);
                split2(acc[am][bn][2], acc[am][bn][3], h23, l23);
                *(uint32_t*)&Chb[(size_t)r0 * N + c0]       = h01;
                *(uint32_t*)&Clb[(size_t)r0 * N + c0]       = l01;
                *(uint32_t*)&Chb[(size_t)(r0 + 8) * N + c0] = h23;
                *(uint32_t*)&Clb[(size_t)(r0 + 8) * N + c0] = l23;
            }
        }
    }
}

// ---------------- split-K reduction kernels ----------------
__global__ void addk_kernel(float* __restrict__ out, int n4)   // out = p0 + p1 (fp32)
{
    const int i = blockIdx.x * 256 + threadIdx.x;
    if (i >= n4) return;
    const float4 a = ((const float4*)g_part)[i];
    const float4 b = ((const float4*)(g_part + (size_t)B_ * S_ * 256))[i];
    ((float4*)out)[i] = make_float4(a.x + b.x, a.y + b.y, a.z + b.z, a.w + b.w);
}

__global__ void addk_split_kernel(__nv_bfloat16* __restrict__ hi,
                                  __nv_bfloat16* __restrict__ lo, int n4)
{
    const int i = blockIdx.x * 256 + threadIdx.x;
    if (i >= n4) return;
    const float4 a = ((const float4*)g_part)[i];
    const float4 b = ((const float4*)(g_part + (size_t)B_ * S_ * 256))[i];
    float4 v = make_float4(a.x + b.x, a.y + b.y, a.z + b.z, a.w + b.w);
    uint32_t h01, l01, h23, l23;
    split2(v.x, v.y, h01, l01);
    split2(v.z, v.w, h23, l23);
    ((uint2*)hi)[i] = make_uint2(h01, h23);
    ((uint2*)lo)[i] = make_uint2(l01, l23);
}

// ---------------- one-time split kernels ----------------
__global__ void split4_kernel(const float* __restrict__ src,
                              __nv_bfloat16* __restrict__ hi,
                              __nv_bfloat16* __restrict__ lo, int n4)
{
    const int i = blockIdx.x * 256 + threadIdx.x;
    if (i >= n4) return;
    float4 v = ((const float4*)src)[i];
    uint32_t h01, l01, h23, l23;
    split2(v.x, v.y, h01, l01);
    split2(v.z, v.w, h23, l23);
    ((uint2*)hi)[i] = make_uint2(h01, h23);
    ((uint2*)lo)[i] = make_uint2(l01, l23);
}

__global__ void concat_split_kernel(const float* __restrict__ a, const float* __restrict__ b,
                                    const float* __restrict__ c, const float* __restrict__ d)
{
    const int i4 = blockIdx.x * 256 + threadIdx.x;
    const int rt = i4 >> 14, rem = i4 & 16383;
    const float* src = (rt == 0) ? a : (rt == 1) ? b : (rt == 2) ? c : d;
    float4 v = ((const float4*)src)[rem];
    uint32_t h01, l01, h23, l23;
    split2(v.x, v.y, h01, l01);
    split2(v.z, v.w, h23, l23);
    ((uint2*)g_whi)[i4] = make_uint2(h01, h23);
    ((uint2*)g_wlo)[i4] = make_uint2(l01, l23);
}

// ---------------- router ----------------
__global__ void router_kernel(const float* __restrict__ importance)
{
    const int rt = blockIdx.x, b = blockIdx.y;
    const int k = (rt == 0) ? KC_ : KE_;
    __shared__ float wpart[8][64];
    __shared__ float w[64];
    const int tid = threadIdx.x, warp = tid >> 5, lane = tid & 31;

    float acc0 = 0.f, acc1 = 0.f;
    for (int s = warp; s < S_; s += 8) {
        const float* lp = g_logits + ((long long)(b * S_ + s)) * 256 + rt * 64;
        float v0 = lp[lane], v1 = lp[lane + 32];
        float mx = fmaxf(v0, v1);
#pragma unroll
        for (int off = 16; off; off >>= 1) mx = fmaxf(mx, __shfl_xor_sync(~0u, mx, off));
        float e0 = __expf(v0 - mx), e1 = __expf(v1 - mx);
        float smv = e0 + e1;
#pragma unroll
        for (int off = 16; off; off >>= 1) smv += __shfl_xor_sync(~0u, smv, off);
        float c = importance[b * S_ + s] / smv;
        acc0 += e0 * c;
        acc1 += e1 * c;
    }
    wpart[warp][lane]      = acc0;
    wpart[warp][lane + 32] = acc1;
    __syncthreads();
    if (tid < 64) {
        float t = 0.f;
#pragma unroll
        for (int wi = 0; wi < 8; wi++) t += wpart[wi][tid];
        w[tid] = t;
    }
    __syncthreads();
    if (tid == 0) {
        float tot = 0.f;
        for (int n = 0; n < 64; n++) tot += w[n];
        const float inv = 1.f / (tot + 1e-8f);
        float tw[16]; int ti[16]; bool used[64];
        for (int n = 0; n < 64; n++) used[n] = false;
        for (int kk = 0; kk < k; kk++) {
            float best = -1e30f; int bi = 0;
            for (int n = 0; n < 64; n++) {
                float v = w[n] * inv;
                if (!used[n] && v > best) { best = v; bi = n; }
            }
            used[bi] = true; tw[kk] = best; ti[kk] = bi;
        }
        float ts = 0.f;
        for (int kk = 0; kk < k; kk++) ts += tw[kk];
        const float inv2 = 1.f / (ts + 1e-8f);
        for (int kk = 0; kk < k; kk++) {
            g_tw[(rt * B_ + b) * 16 + kk] = tw[kk] * inv2;
            g_ti[(rt * B_ + b) * 16 + kk] = ti[kk];
        }
    }
}

// ---------------- mix compress -> split bf16 [b][r][d] -----
__global__ void mix_compressT_kernel(const float* __restrict__ cn)
{
    const int b = blockIdx.y;
    const int dt = blockIdx.x >> 3, rt = blockIdx.x & 7;
    const int d0 = dt * 32, r0 = rt * 32;
    __shared__ float cw[KC_]; __shared__ int ci[KC_];
    __shared__ float ts[32][33];
    if (threadIdx.x < KC_) {
        cw[threadIdx.x] = g_tw[(0 * B_ + b) * 16 + threadIdx.x];
        ci[threadIdx.x] = g_ti[(0 * B_ + b) * 16 + threadIdx.x];
    }
    __syncthreads();
    const int tid = threadIdx.x;
    const int dd = tid >> 3, rr = (tid & 7) << 2;
    float4 acc = {0.f, 0.f, 0.f, 0.f};
#pragma unroll
    for (int kk = 0; kk < KC_; kk++) {
        const float4 v = *(const float4*)(cn + ((size_t)ci[kk] * D_ + d0 + dd) * R_ + r0 + rr);
        const float wv = cw[kk];
        acc.x += wv * v.x; acc.y += wv * v.y; acc.z += wv * v.z; acc.w += wv * v.w;
    }
    ts[dd][rr] = acc.x; ts[dd][rr + 1] = acc.y; ts[dd][rr + 2] = acc.z; ts[dd][rr + 3] = acc.w;
    __syncthreads();
    const int rw = tid >> 3, dw = (tid & 7) << 2;
    float4 o = {ts[dw][rw], ts[dw + 1][rw], ts[dw + 2][rw], ts[dw + 3][rw]};
    uint32_t h01, l01, h23, l23;
    split2(o.x, o.y, h01, l01);
    split2(o.z, o.w, h23, l23);
    const size_t base = ((size_t)b * R_ + r0 + rw) * D_ + d0 + dw;
    *(uint2*)&g_schi[base] = make_uint2(h01, h23);
    *(uint2*)&g_sclo[base] = make_uint2(l01, l23);
}

// ---------------- mix expand -> split bf16 [b][3D][r] --
__global__ void mix_expandT_kernel(const float* __restrict__ pool)
{
    const int which = blockIdx.y, b = blockIdx.z;
    const int dt = blockIdx.x >> 3, rt = blockIdx.x & 7;
    const int d0 = dt * 32, r0 = rt * 32;
    const int rtr = which + 1;
    __shared__ float ew[KE_]; __shared__ int ei[KE_];
    __shared__ float ts[32][33];
    if (threadIdx.x < KE_) {
        ew[threadIdx.x] = g_tw[(rtr * B_ + b) * 16 + threadIdx.x];
        ei[threadIdx.x] = g_ti[(rtr * B_ + b) * 16 + threadIdx.x];
    }
    __syncthreads();
    const int tid = threadIdx.x;
    const int rr = tid >> 3, dd = (tid & 7) << 2;
    float4 acc = {0.f, 0.f, 0.f, 0.f};
#pragma unroll
    for (int kk = 0; kk < KE_; kk++) {
        const float4 v = *(const float4*)(pool + ((size_t)ei[kk] * R_ + r0 + rr) * D_ + d0 + dd);
        const float wv = ew[kk];
        acc.x += wv * v.x; acc.y += wv * v.y; acc.z += wv * v.z; acc.w += wv * v.w;
    }
    ts[rr][dd] = acc.x; ts[rr][dd + 1] = acc.y; ts[rr][dd + 2] = acc.z; ts[rr][dd + 3] = acc.w;
    __syncthreads();
    const int dw = tid >> 3, rw = (tid & 7) << 2;
    float4 o = {ts[rw][dw], ts[rw + 1][dw], ts[rw + 2][dw], ts[rw + 3][dw]};
    uint32_t h01, l01, h23, l23;
    split2(o.x, o.y, h01, l01);
    split2(o.z, o.w, h23, l23);
    const size_t base = ((size_t)b * 3 * D_ + (size_t)which * D_ + d0 + dw) * R_ + r0 + rw;
    *(uint2*)&g_ehi[base] = make_uint2(h01, h23);
    *(uint2*)&g_elo[base] = make_uint2(l01, l23);
}

// =======================================================================
// flash attention (proven R10 config), 2 CTA/SM
// =======================================================================
#define FPX 72
#define FQHI 0
#define FQLO (128 * FPX)
#define FKV0 (256 * FPX)
#define KVSZ (256 * FPX)
#define FLASH_SMEM ((FKV0 + 2 * KVSZ) * 2)     // 110592 bytes
#define SC2L 0.18033688011112042f

__global__ __launch_bounds__(256, 2) void flash_mma_bf(
    const __nv_bfloat16* __restrict__ qh, const __nv_bfloat16* __restrict__ ql,
    __nv_bfloat16* __restrict__ oh, __nv_bfloat16* __restrict__ ol)
{
    extern __shared__ char smc[];
    const uint32_t smb = smem_u32(smc);
    const int tid = threadIdx.x, w = tid >> 5, lane = tid & 31;
    const int b = blockIdx.y >> 4, h = blockIdx.y & 15;
    const int q0 = blockIdx.x * 128;
    const size_t bbase = (size_t)b * S_ * (3 * D_) + h * DH_;

    auto issue_kv = [&](int t) {
        const int k0 = t * 64;
        const uint32_t kvb = (uint32_t)(FKV0 + (t & 1) * KVSZ);
#pragma unroll
        for (int q = 0; q < 8; ++q) {
            const int c = q * 256 + tid;
            const int tile = c >> 9, rem = c & 511;
            const int row = rem >> 3, c16 = rem & 7;
            const uint32_t dst = smb + 2 * (kvb + tile * (64 * FPX) + row * FPX) + c16 * 16;
            const __nv_bfloat16* sp = (tile & 1) ? ql : qh;
            const size_t goff = bbase + ((tile >> 1) ? 2 * D_ : D_)
                                + (size_t)(k0 + row) * (3 * D_) + c16 * 8;
            CP16(dst, sp + goff);
        }
    };

#pragma unroll
    for (int q = 0; q < 8; ++q) {
        const int c = q * 256 + tid;
        const int arr = c >> 10, rem = c & 1023;
        const int row = rem >> 3, c16 = rem & 7;
        const uint32_t dst = smb + (arr ? FQLO : FQHI) * 2 + row * (FPX * 2) + c16 * 16;
        const __nv_bfloat16* src = (arr ? ql : qh) + bbase
                                   + (size_t)(q0 + row) * (3 * D_) + c16 * 8;
        CP16(dst, src);
    }
    issue_kv(0); CPCOMMIT();

    float sacc[8][4], oacc[8][4];
    float m0v = -1e30f, m1v = -1e30f, l0v = 0.f, l1v = 0.f;
#pragma unroll
    for (int t = 0; t < 8; t++)
#pragma unroll
        for (int e = 0; e < 4; e++) oacc[t][e] = 0.f;

    const int a_row = lane & 15;
    const int a_kad = (lane >> 4) << 3;
    const int b_row = (lane & 7) + ((lane & 16) >> 1);
    const int b_kad = lane & 8;
    const int qwarp = q0 + w * 16;
    const int r0 = lane >> 2;
    const int c0l = (lane & 3) << 1;

    const int ntiles = (q0 + 128) >> 6;
    for (int t = 0; t < ntiles; ++t) {
        const int k0 = t * 64;
        if (t + 1 < ntiles) { issue_kv(t + 1); CPCOMMIT(); CPWAIT1(); }
        else                { CPWAIT0(); }
        __syncthreads();

        if (k0 <= qwarp + 15) {
            const uint32_t kv = (uint32_t)(FKV0 + (t & 1) * KVSZ);
#pragma unroll
            for (int tt = 0; tt < 8; tt++)
#pragma unroll
                for (int e = 0; e < 4; e++) sacc[tt][e] = 0.f;
#pragma unroll
            for (int kk = 0; kk < 4; ++kk) {
                uint32_t qhf[4], qlf[4];
                const uint32_t qoff = 2 * (uint32_t)((w * 16 + a_row) * FPX + kk * 16 + a_kad);
                ldm_x4(qhf, smb + 2 * FQHI + qoff);
                ldm_x4(qlf, smb + 2 * FQLO + qoff);
#pragma unroll
                for (int jt = 0; jt < 4; ++jt) {
                    uint32_t khf[4], klf[4];
                    const uint32_t koff = 2 * (uint32_t)(kv + (jt * 16 + b_row) * FPX
                                                         + kk * 16 + b_kad);
                    ldm_x4(khf, smb + koff);
                    ldm_x4(klf, smb + koff + 2 * (64 * FPX));
                    mma16816(sacc[jt * 2],     qhf, khf);
                    mma16816(sacc[jt * 2 + 1], qhf, khf + 2);
                    mma16816(sacc[jt * 2],     qhf, klf);
                    mma16816(sacc[jt * 2 + 1], qhf, klf + 2);
                    mma16816(sacc[jt * 2],     qlf, khf);
                    mma16816(sacc[jt * 2 + 1], qlf, khf + 2);
                }
            }

            if (k0 + 63 > qwarp) {
#pragma unroll
                for (int tt = 0; tt < 8; tt++) {
                    const int kg = k0 + tt * 8 + c0l;
#pragma unroll
                    for (int e = 0; e < 4; e++) {
                        const int kge = kg + (e & 1);
                        const int qg = qwarp + r0 + ((e >> 1) << 3);
                        if (kge > qg) sacc[tt][e] = -1e30f;
                    }
                }
            }

            float mx0 = -1e30f, mx1 = -1e30f;
#pragma unroll
            for (int tt = 0; tt < 8; tt++) {
                mx0 = fmaxf(mx0, fmaxf(sacc[tt][0], sacc[tt][1]));
                mx1 = fmaxf(mx1, fmaxf(sacc[tt][2], sacc[tt][3]));
            }
            mx0 = fmaxf(mx0, __shfl_xor_sync(~0u, mx0, 1));
            mx0 = fmaxf(mx0, __shfl_xor_sync(~0u, mx0, 2));
            mx1 = fmaxf(mx1, __shfl_xor_sync(~0u, mx1, 1));
            mx1 = fmaxf(mx1, __shfl_xor_sync(~0u, mx1, 2));
            const float mn0 = fmaxf(m0v, mx0), mn1 = fmaxf(m1v, mx1);
            const float al0 = exp2f((m0v - mn0) * SC2L);
            const float al1 = exp2f((m1v - mn1) * SC2L);
            float sum0 = 0.f, sum1 = 0.f;
            uint32_t ph[8][2], pl[8][2];
#pragma unroll
            for (int tt = 0; tt < 8; tt++) {
                float p0 = exp2f((sacc[tt][0] - mn0) * SC2L);
                float p1 = exp2f((sacc[tt][1] - mn0) * SC2L);
                float p2 = exp2f((sacc[tt][2] - mn1) * SC2L);
                float p3 = exp2f((sacc[tt][3] - mn1) * SC2L);
                sum0 += p0 + p1; sum1 += p2 + p3;
                split2(p0, p1, ph[tt][0], pl[tt][0]);
                split2(p2, p3, ph[tt][1], pl[tt][1]);
            }
            sum0 += __shfl_xor_sync(~0u, sum0, 1);
            sum0 += __shfl_xor_sync(~0u, sum0, 2);
            sum1 += __shfl_xor_sync(~0u, sum1, 1);
            sum1 += __shfl_xor_sync(~0u, sum1, 2);
            l0v = l0v * al0 + sum0;
            l1v = l1v * al1 + sum1;
            m0v = mn0; m1v = mn1;
#pragma unroll
            for (int tt = 0; tt < 8; tt++) {
                oacc[tt][0] *= al0; oacc[tt][1] *= al0;
                oacc[tt][2] *= al1; oacc[tt][3] *= al1;
            }

#pragma unroll
            for (int g = 0; g < 4; ++g) {
                uint32_t Ahf[4] = {ph[2 * g][0], ph[2 * g][1], ph[2 * g + 1][0], ph[2 * g + 1][1]};
                uint32_t Alf[4] = {pl[2 * g][0], pl[2 * g][1], pl[2 * g + 1][0], pl[2 * g + 1][1]};
#pragma unroll
                for (int dp = 0; dp < 4; ++dp) {
                    uint32_t vhf[4], vlf[4];
                    const uint32_t voff = 2 * (uint32_t)(kv + 128 * FPX
                                                         + (g * 16 + (lane & 15)) * FPX
                                                         + dp * 16 + ((lane >> 4) << 3));
                    ldm_x4t(vhf, smb + voff);
                    ldm_x4t(vlf, smb + voff + 2 * (64 * FPX));
                    mma16816(oacc[dp * 2],     Ahf, vhf);
                    mma16816(oacc[dp * 2 + 1], Ahf, vhf + 2);
                    mma16816(oacc[dp * 2],     Alf, vhf);
                    mma16816(oacc[dp * 2 + 1], Alf, vhf + 2);
                    mma16816(oacc[dp * 2],     Ahf, vlf);
                    mma16816(oacc[dp * 2 + 1], Ahf, vlf + 2);
                }
            }
        }
        __syncthreads();
    }

    const float inv0 = 1.f / l0v, inv1 = 1.f / l1v;
    __nv_bfloat16* ohp = oh + (size_t)b * S_ * D_ + (size_t)h * DH_;
    __nv_bfloat16* olp = ol + (size_t)b * S_ * D_ + (size_t)h * DH_;
    const int row0 = q0 + w * 16 + r0;
#pragma unroll
    for (int t = 0; t < 8; t++) {
        const int c = t * 8 + c0l;
        uint32_t h01, l01, h23, l23;
        split2(oacc[t][0] * inv0, oacc[t][1] * inv0, h01, l01);
        split2(oacc[t][2] * inv1, oacc[t][3] * inv1, h23, l23);
        *(uint32_t*)&ohp[(size_t)row0 * D_ + c]       = h01;
        *(uint32_t*)&olp[(size_t)row0 * D_ + c]       = l01;
        *(uint32_t*)&ohp[(size_t)(row0 + 8) * D_ + c] = h23;
        *(uint32_t*)&olp[(size_t)(row0 + 8) * D_ + c] = l23;
    }
}

// ---------------- launch ----------------
extern "C" void kernel_launch(void* const* d_in, const int* in_sizes, int n_in,
                              void* d_out, int out_size)
{
    const float* x    = (const float*)d_in[0];
    const float* imp  = (const float*)d_in[1];
    const float* Wc   = (const float*)d_in[2];
    const float* Wq   = (const float*)d_in[3];
    const float* Wk   = (const float*)d_in[4];
    const float* Wv   = (const float*)d_in[5];
    const float* cn   = (const float*)d_in[6];
    const float* pool = (const float*)d_in[7];
    const float* WO   = (const float*)d_in[8];
    float* out = (float*)d_out;

    float *pLog, *pPart;
    __nv_bfloat16 *pxh, *pxl, *pwh, *pwl, *psh, *psl, *phh, *phl;
    __nv_bfloat16 *peh, *pel, *pqh, *pql, *pah, *pal, *poh2, *pol2;
    cudaGetSymbolAddress((void**)&pLog, g_logits);
    cudaGetSymbolAddress((void**)&pPart, g_part);
    cudaGetSymbolAddress((void**)&pxh, g_xhi);  cudaGetSymbolAddress((void**)&pxl, g_xlo);
    cudaGetSymbolAddress((void**)&pwh, g_whi);  cudaGetSymbolAddress((void**)&pwl, g_wlo);
    cudaGetSymbolAddress((void**)&psh, g_schi); cudaGetSymbolAddress((void**)&psl, g_sclo);
    cudaGetSymbolAddress((void**)&phh, g_hhi);  cudaGetSymbolAddress((void**)&phl, g_hlo);
    cudaGetSymbolAddress((void**)&peh, g_ehi);  cudaGetSymbolAddress((void**)&pel, g_elo);
    cudaGetSymbolAddress((void**)&pqh, g_qhi);  cudaGetSymbolAddress((void**)&pql, g_qlo);
    cudaGetSymbolAddress((void**)&pah, g_aohi); cudaGetSymbolAddress((void**)&pal, g_aolo);
    cudaGetSymbolAddress((void**)&poh2, g_wohi); cudaGetSymbolAddress((void**)&pol2, g_wolo);

    cudaFuncSetAttribute(mma_gemm_bf<0,0>, cudaFuncAttributeMaxDynamicSharedMemorySize, GEMM_SMEM);
    cudaFuncSetAttribute(mma_gemm_bf<0,1>, cudaFuncAttributeMaxDynamicSharedMemorySize, GEMM_SMEM);
    cudaFuncSetAttribute(mma_gemm_bf<1,0>, cudaFuncAttributeMaxDynamicSharedMemorySize, GEMM_SMEM);
    cudaFuncSetAttribute(flash_mma_bf, cudaFuncAttributeMaxDynamicSharedMemorySize, FLASH_SMEM);

    const long long PHALF = (long long)B_ * S_ * 256;   // partial buffer half (2M floats)

    // one-time splits
    split4_kernel<<<8192, 256>>>(x, pxh, pxl, B_ * S_ * D_ / 4);
    concat_split_kernel<<<256, 256>>>(Wc, Wq, Wk, Wv);
    split4_kernel<<<1024, 256>>>(WO, poh2, pol2, D_ * D_ / 4);

    // logits = x @ Wall^T  -- split-K=2 (grid 256), partials then add
    mma_gemm_bf<0,1><<<dim3(64, 2, 2), 256, GEMM_SMEM>>>(
        pxh, pxl, pwh, pwl, pPart, nullptr, nullptr,
        8192, 256, 512, 1024, 0, 0, 0, PHALF);
    addk_kernel<<<2048, 256>>>(pLog, B_ * S_ * 256 / 4);
    router_kernel<<<dim3(4, 8), 256>>>(imp);
    mix_compressT_kernel<<<dim3(256, 8), 256>>>(cn);
    // h = x @ sharedc^T  -- split-K=2 (grid 256), partials then add+split
    mma_gemm_bf<0,1><<<dim3(8, 2, 16), 256, GEMM_SMEM>>>(
        pxh, pxl, psh, psl, pPart, nullptr, nullptr,
        1024, 256, 512, 1024, (long long)S_ * D_, (long long)R_ * D_,
        (long long)S_ * R_, PHALF);
    addk_split_kernel<<<2048, 256>>>(phh, phl, B_ * S_ * R_ / 4);
    mix_expandT_kernel<<<dim3(256, 3, 8), 256>>>(pool);
    // qkv = h @ eAll^T (no split-K; grid 1536 fills chip)
    mma_gemm_bf<1,0><<<dim3(8, 24, 8), 256, GEMM_SMEM>>>(
        phh, phl, peh, pel, nullptr, pqh, pql,
        1024, 3 * D_, 256, 256, (long long)S_ * R_, (long long)3 * D_ * R_,
        (long long)S_ * 3 * D_, 0);
    // flash attention
    flash_mma_bf<<<dim3(8, 128), 256, FLASH_SMEM>>>(pqh, pql, pah, pal);
    // out = aout @ W_O^T (grid 512)
    mma_gemm_bf<0,0><<<dim3(64, 8, 1), 256, GEMM_SMEM>>>(
        pah, pal, poh2, pol2, out, nullptr, nullptr,
        8192, 1024, 1024, 1024, 0, 0, 0, 0);
}